// round 8
// baseline (speedup 1.0000x reference)
#include <cuda_runtime.h>
#include <math.h>

#define KC 16
#define DD 32
#define NQ 289                 // packed term-pairs over augmented dim 33
#define TM 128                 // M-step tile (samples)
#define NBANK 8
#define LOG2PIF 1.8378770664093453f
#define REGC 1e-6f
#define RESP_EPSF 1.1920928955078125e-6f   // 10 * eps(float32)
#define NMAX 100000

typedef unsigned long long ull;

// ---------------- f32x2 helpers ----------------
__device__ __forceinline__ void ffma2(ull& acc, ull a, ull b) {
    asm("fma.rn.f32x2 %0, %1, %2, %0;" : "+l"(acc) : "l"(a), "l"(b));
}
__device__ __forceinline__ ull mul2(ull a, ull b) {
    ull r; asm("mul.rn.f32x2 %0, %1, %2;" : "=l"(r) : "l"(a), "l"(b)); return r;
}
__device__ __forceinline__ ull pk(float a, float b) {
    ull r; asm("mov.b64 %0, {%1, %2};" : "=l"(r) : "f"(a), "f"(b)); return r;
}
__device__ __forceinline__ float2 upk(ull a) {
    float2 f; asm("mov.b64 {%0, %1}, %2;" : "=f"(f.x), "=f"(f.y) : "l"(a)); return f;
}

// ---------------- device state ----------------
__device__ float g_w[KC];
__device__ float g_means[KC][DD];
__device__ float g_cov[KC][DD][DD];
__device__ __align__(16) float g_cf2[NQ * 32];     // [q][k][2] packed coefs
__device__ __align__(16) float g_resp[NMAX * KC];
__device__ float g_nkb[NBANK][KC];
__device__ float g_sumxb[NBANK][KC][DD];
__device__ float g_Sb[NBANK][KC][DD][DD];

// ---------------- init ----------------
__global__ void init_k(const float* __restrict__ w, const float* __restrict__ m,
                       const float* __restrict__ c) {
    int tid = blockIdx.x * blockDim.x + threadIdx.x;
    int tot = gridDim.x * blockDim.x;
    for (int i = tid; i < KC * DD * DD; i += tot) ((float*)g_cov)[i] = c[i];
    for (int i = tid; i < KC * DD; i += tot) ((float*)g_means)[i] = m[i];
    if (tid == 0) {
        float s = 0.f;
        for (int k = 0; k < KC; k++) s += w[k];
        for (int k = 0; k < KC; k++) g_w[k] = w[k] / s;
    }
}

// ---------------- prep: (optional bank-reduce -> new params) + Cholesky -> coefs ----------------
// 16 blocks (component each), 32 threads.
__global__ void prep_k(int N, int first) {
    __shared__ float A[DD][DD + 1];
    __shared__ float bsh[DD];
    __shared__ float msh[DD];
    __shared__ float csh, nksh;
    int k = blockIdx.x;
    int lane = threadIdx.x;

    if (!first) {
        // reduce banks -> nk, means, weights
        if (lane == 0) {
            float s = 0.f;
            for (int b = 0; b < NBANK; b++) s += g_nkb[b][k];
            nksh = s + RESP_EPSF;
            g_w[k] = nksh / (float)N;
        }
        __syncwarp();
        float nk = nksh;
        {
            float sx = 0.f;
            for (int b = 0; b < NBANK; b++) sx += g_sumxb[b][k][lane];
            float mm = sx / nk;
            msh[lane] = mm;
            g_means[k][lane] = mm;
        }
        __syncwarp();
        // cov = S/nk - m m^T + REG (stored convention) ; +REG again for chol
        for (int i = lane; i < DD * DD; i += 32) {
            int r = i >> 5, c = i & 31;
            float s = 0.f;
            for (int b = 0; b < NBANK; b++) s += ((float*)g_Sb[b][k])[i];
            A[r][c] = s / nk - msh[r] * msh[c] + (r == c ? 2.f * REGC : 0.f);
        }
    } else {
        for (int i = lane; i < DD * DD; i += 32) {
            int r = i >> 5, c = i & 31;
            A[r][c] = g_cov[k][r][c] + (r == c ? REGC : 0.f);
        }
    }
    __syncwarp();

    // zero banked accumulators for this component (for the next m_k)
    for (int i = lane; i < NBANK * DD * DD; i += 32) {
        int b = i / (DD * DD);
        ((float*)g_Sb[b][k])[i - b * DD * DD] = 0.f;
    }
    for (int i = lane; i < NBANK * DD; i += 32) g_sumxb[i >> 5][k][i & 31] = 0.f;
    if (lane < NBANK) g_nkb[lane][k] = 0.f;

    // Cholesky (lower), lane = row
    for (int j = 0; j < DD; j++) {
        float ljj = sqrtf(A[j][j]);
        __syncwarp();
        if (lane == j) A[j][j] = ljj;
        else if (lane > j) A[lane][j] = A[lane][j] / ljj;
        __syncwarp();
        if (lane > j) {
            float lij = A[lane][j];
            for (int c2 = j + 1; c2 <= lane; c2++) A[lane][c2] -= lij * A[c2][j];
        }
        __syncwarp();
    }

    float logdet = 0.f;
    for (int j = 0; j < DD; j++) logdet += logf(A[j][j]);

    // P = L^{-T} L^{-1}; lane computes column `lane`
    float y[DD];
#pragma unroll
    for (int r = 0; r < DD; r++) y[r] = (r == lane) ? 1.f : 0.f;
#pragma unroll
    for (int j = 0; j < DD; j++) {
        y[j] = y[j] / A[j][j];
#pragma unroll
        for (int i2 = j + 1; i2 < DD; i2++) y[i2] -= A[i2][j] * y[j];
    }
#pragma unroll
    for (int j = DD - 1; j >= 0; j--) {
        y[j] = y[j] / A[j][j];
#pragma unroll
        for (int i2 = 0; i2 < j; i2++) y[i2] -= A[j][i2] * y[j];
    }
    __syncwarp();
#pragma unroll
    for (int r = 0; r < DD; r++) A[r][lane] = y[r];   // A := P
    __syncwarp();

    // b = P * mu
    float b = 0.f;
    for (int j = 0; j < DD; j++) b += A[lane][j] * g_means[k][j];
    bsh[lane] = b;
    float cv = b * g_means[k][lane];
    for (int o = 16; o; o >>= 1) cv += __shfl_xor_sync(0xffffffff, cv, o);
    if (lane == 0)
        csh = logf(g_w[k]) - logdet - 0.5f * cv - 0.5f * (float)DD * LOG2PIF;
    __syncwarp();

    // pack coefs (augmented x, x[32]=1): terms (i,j) 0<=i<=j<=32, consecutive-j pairs
    for (int q = lane; q < NQ; q += 32) {
        int i = 0, qq = q;
        while (true) {
            int np = (34 - i) >> 1;
            if (qq < np) break;
            qq -= np; i++;
        }
        int j = i + 2 * qq;
        float c0, c1;
        {
            int jj = j;
            if (i == 32) c0 = csh;
            else if (jj == 32) c0 = bsh[i];
            else c0 = (i == jj ? -0.5f : -1.0f) * A[i][jj];
        }
        if (j + 1 <= 32) {
            int jj = j + 1;
            if (jj == 32) c1 = bsh[i];
            else c1 = (i == jj ? -0.5f : -1.0f) * A[i][jj];
        } else c1 = 0.f;
        g_cf2[q * 32 + k * 2] = c0;
        g_cf2[q * 32 + k * 2 + 1] = c1;
    }
}

// ---------------- E kernel: 2 samples/thread, f32x2, 255-reg budget ----------------
__global__ void __launch_bounds__(256, 1) e_k(const float* __restrict__ X,
                                              float* __restrict__ out,
                                              int N, int mode) {
    __shared__ __align__(16) float cf[NQ * 32];
    for (int i = threadIdx.x; i < NQ * 8; i += 256)
        ((float4*)cf)[i] = ((const float4*)g_cf2)[i];
    __syncthreads();

    int n0 = (blockIdx.x * 256 + threadIdx.x) * 2;
    int n1 = n0 + 1;
    bool vA = n0 < N, vB = n1 < N;
    if (!vA) return;

    float xa[34], xb[34];
    {
        const float4* xp = (const float4*)(X + (size_t)n0 * DD);
#pragma unroll
        for (int j4 = 0; j4 < 8; j4++) {
            float4 v = xp[j4];
            xa[j4 * 4 + 0] = v.x; xa[j4 * 4 + 1] = v.y;
            xa[j4 * 4 + 2] = v.z; xa[j4 * 4 + 3] = v.w;
        }
        const float4* xq = (const float4*)(X + (size_t)(vB ? n1 : n0) * DD);
#pragma unroll
        for (int j4 = 0; j4 < 8; j4++) {
            float4 v = xq[j4];
            xb[j4 * 4 + 0] = v.x; xb[j4 * 4 + 1] = v.y;
            xb[j4 * 4 + 2] = v.z; xb[j4 * 4 + 3] = v.w;
        }
    }
    xa[32] = 1.f; xa[33] = 0.f;
    xb[32] = 1.f; xb[33] = 0.f;

    ull lpa[KC], lpb[KC];
#pragma unroll
    for (int k = 0; k < KC; k++) { lpa[k] = 0ull; lpb[k] = 0ull; }

    int q = 0;
#pragma unroll
    for (int i = 0; i < 33; i++) {
        ull xia = pk(xa[i], xa[i]);
        ull xib = pk(xb[i], xb[i]);
#pragma unroll
        for (int j = i; j < 33; j += 2) {
            ull xxa = mul2(xia, pk(xa[j], xa[j + 1]));
            ull xxb = mul2(xib, pk(xb[j], xb[j + 1]));
            const float* cq = cf + q * 32;
#pragma unroll
            for (int kb = 0; kb < 8; kb++) {
                ulonglong2 cc = *(const ulonglong2*)(cq + kb * 4);
                ffma2(lpa[kb * 2 + 0], cc.x, xxa);
                ffma2(lpa[kb * 2 + 1], cc.y, xxa);
                ffma2(lpb[kb * 2 + 0], cc.x, xxb);
                ffma2(lpb[kb * 2 + 1], cc.y, xxb);
            }
            q++;
        }
    }

    // epilogue (both samples)
    float la[KC], lb[KC];
#pragma unroll
    for (int k = 0; k < KC; k++) {
        float2 fa = upk(lpa[k]); la[k] = fa.x + fa.y;
        float2 fb = upk(lpb[k]); lb[k] = fb.x + fb.y;
    }
    float ma = la[0], mb = lb[0];
#pragma unroll
    for (int k = 1; k < KC; k++) { ma = fmaxf(ma, la[k]); mb = fmaxf(mb, lb[k]); }
    float sa = 0.f, sb = 0.f;
#pragma unroll
    for (int k = 0; k < KC; k++) {
        la[k] = __expf(la[k] - ma); sa += la[k];
        lb[k] = __expf(lb[k] - mb); sb += lb[k];
    }

    if (mode == 1) {
        out[n0] = ma + __logf(sa);
        if (vB) out[n1] = mb + __logf(sb);
    } else {
        float ia = 1.f / sa, ib = 1.f / sb;
        float4* rp = (float4*)(g_resp + (size_t)n0 * KC);
#pragma unroll
        for (int k4 = 0; k4 < 4; k4++)
            rp[k4] = make_float4(la[k4 * 4 + 0] * ia, la[k4 * 4 + 1] * ia,
                                 la[k4 * 4 + 2] * ia, la[k4 * 4 + 3] * ia);
        if (vB) {
            float4* rq = (float4*)(g_resp + (size_t)n1 * KC);
#pragma unroll
            for (int k4 = 0; k4 < 4; k4++)
                rq[k4] = make_float4(lb[k4 * 4 + 0] * ib, lb[k4 * 4 + 1] * ib,
                                     lb[k4 * 4 + 2] * ib, lb[k4 * 4 + 3] * ib);
        }
    }
}

// ---------------- M kernel: 512 threads, thread = (k, one row), high occupancy ----------------
__global__ void __launch_bounds__(512) m_k(const float* __restrict__ X,
                                           int N, int ntiles) {
    __shared__ __align__(16) float x2[TM * 36];
    __shared__ float rs[TM * 17];
    int tid = threadIdx.x;
    int k = tid & 15;
    int i = tid >> 4;          // 0..31

    ull acc[16];
#pragma unroll
    for (int m = 0; m < 16; m++) acc[m] = 0ull;
    float aX = 0.f, aN = 0.f;

    for (int tile = blockIdx.x; tile < ntiles; tile += gridDim.x) {
        int base = tile * TM;
        int cnt = N - base; if (cnt > TM) cnt = TM;
        __syncthreads();
        for (int e = tid; e < TM * DD; e += 512) {
            int s = e >> 5, d = e & 31;
            x2[s * 36 + d] = (s < cnt) ? X[(size_t)(base + s) * DD + d] : 0.f;
        }
        for (int e = tid; e < TM * KC; e += 512) {
            int s = e >> 4, kk = e & 15;
            rs[s * 17 + kk] = (s < cnt) ? g_resp[(size_t)(base + s) * KC + kk] : 0.f;
        }
        __syncthreads();

#pragma unroll 2
        for (int t = 0; t < TM; t++) {
            float r = rs[t * 17 + k];
            float xi = x2[t * 36 + i];
            float u = r * xi;
            aX += u;
            if (i == 0) aN += r;
            ull u2 = pk(u, u);
            const ulonglong2* xv = (const ulonglong2*)&x2[t * 36];
#pragma unroll
            for (int j2 = 0; j2 < 8; j2++) {
                ulonglong2 v = xv[j2];
                ffma2(acc[j2 * 2 + 0], u2, v.x);
                ffma2(acc[j2 * 2 + 1], u2, v.y);
            }
        }
    }

    int bank = blockIdx.x & (NBANK - 1);
#pragma unroll
    for (int m = 0; m < 16; m++) {
        float2 a = upk(acc[m]);
        atomicAdd(&g_Sb[bank][k][i][2 * m + 0], a.x);
        atomicAdd(&g_Sb[bank][k][i][2 * m + 1], a.y);
    }
    atomicAdd(&g_sumxb[bank][k][i], aX);
    if (i == 0) atomicAdd(&g_nkb[bank][k], aN);
}

// ---------------- host launcher ----------------
extern "C" void kernel_launch(void* const* d_in, const int* in_sizes, int n_in,
                              void* d_out, int out_size) {
    const float* X = (const float*)d_in[0];
    const float* w = (const float*)d_in[1];
    const float* m = (const float*)d_in[2];
    const float* c = (const float*)d_in[3];
    float* out = (float*)d_out;

    int N = in_sizes[0] / DD;
    int ntiles = (N + TM - 1) / TM;
    int egrid = (N + 511) / 512;
    int mgrid = 296;
    if (mgrid > ntiles) mgrid = ntiles;

    init_k<<<34, 512>>>(w, m, c);
    for (int it = 0; it < 5; it++) {       // n_iter = 5 (fixed problem instance)
        prep_k<<<KC, 32>>>(N, it == 0 ? 1 : 0);
        e_k<<<egrid, 256>>>(X, nullptr, N, 0);
        m_k<<<mgrid, 512>>>(X, N, ntiles);
    }
    prep_k<<<KC, 32>>>(N, 0);
    e_k<<<egrid, 256>>>(X, out, N, 1);
}

// round 9
// speedup vs baseline: 1.0106x; 1.0106x over previous
#include <cuda_runtime.h>
#include <math.h>

#define KC 16
#define DD 32
#define NQ 289                 // packed term-pairs over augmented dim 33
#define TM 128                 // M-step tile (samples)
#define NBANK 8
#define LOG2PIF 1.8378770664093453f
#define REGC 1e-6f
#define RESP_EPSF 1.1920928955078125e-6f   // 10 * eps(float32)
#define NMAX 100000

typedef unsigned long long ull;

// ---------------- f32x2 helpers ----------------
__device__ __forceinline__ void ffma2(ull& acc, ull a, ull b) {
    asm("fma.rn.f32x2 %0, %1, %2, %0;" : "+l"(acc) : "l"(a), "l"(b));
}
__device__ __forceinline__ ull mul2(ull a, ull b) {
    ull r; asm("mul.rn.f32x2 %0, %1, %2;" : "=l"(r) : "l"(a), "l"(b)); return r;
}
__device__ __forceinline__ ull pk(float a, float b) {
    ull r; asm("mov.b64 %0, {%1, %2};" : "=l"(r) : "f"(a), "f"(b)); return r;
}
__device__ __forceinline__ float2 upk(ull a) {
    float2 f; asm("mov.b64 {%0, %1}, %2;" : "=f"(f.x), "=f"(f.y) : "l"(a)); return f;
}

// ---------------- device state ----------------
__device__ float g_w[KC];
__device__ float g_means[KC][DD];
__device__ float g_cov[KC][DD][DD];
__device__ __align__(16) float g_cf2[NQ * 32];     // [q][k][2] packed coefs
__device__ __align__(16) float g_resp[NMAX * KC];
__device__ float g_nkb[NBANK][KC];
__device__ float g_sumxb[NBANK][KC][DD];
__device__ float g_Sb[NBANK][KC][DD][DD];

// ---------------- init ----------------
__global__ void init_k(const float* __restrict__ w, const float* __restrict__ m,
                       const float* __restrict__ c) {
    int tid = blockIdx.x * blockDim.x + threadIdx.x;
    int tot = gridDim.x * blockDim.x;
    for (int i = tid; i < KC * DD * DD; i += tot) ((float*)g_cov)[i] = c[i];
    for (int i = tid; i < KC * DD; i += tot) ((float*)g_means)[i] = m[i];
    if (tid == 0) {
        float s = 0.f;
        for (int k = 0; k < KC; k++) s += w[k];
        for (int k = 0; k < KC; k++) g_w[k] = w[k] / s;
    }
}

// ---------------- prep: (optional bank-reduce -> new params) + Cholesky -> coefs ----------------
// 16 blocks (component each), 32 threads.
__global__ void prep_k(int N, int first) {
    __shared__ float A[DD][DD + 1];
    __shared__ float bsh[DD];
    __shared__ float msh[DD];
    __shared__ float csh, nksh;
    int k = blockIdx.x;
    int lane = threadIdx.x;

    if (!first) {
        // reduce banks -> nk, means, weights
        if (lane == 0) {
            float s = 0.f;
            for (int b = 0; b < NBANK; b++) s += g_nkb[b][k];
            nksh = s + RESP_EPSF;
            g_w[k] = nksh / (float)N;
        }
        __syncwarp();
        float nk = nksh;
        {
            float sx = 0.f;
            for (int b = 0; b < NBANK; b++) sx += g_sumxb[b][k][lane];
            float mm = sx / nk;
            msh[lane] = mm;
            g_means[k][lane] = mm;
        }
        __syncwarp();
        // cov = S/nk - m m^T + REG (stored convention) ; +REG again for chol
        for (int i = lane; i < DD * DD; i += 32) {
            int r = i >> 5, c = i & 31;
            float s = 0.f;
            for (int b = 0; b < NBANK; b++) s += ((float*)g_Sb[b][k])[i];
            A[r][c] = s / nk - msh[r] * msh[c] + (r == c ? 2.f * REGC : 0.f);
        }
    } else {
        for (int i = lane; i < DD * DD; i += 32) {
            int r = i >> 5, c = i & 31;
            A[r][c] = g_cov[k][r][c] + (r == c ? REGC : 0.f);
        }
    }
    __syncwarp();

    // zero banked accumulators for this component (for the next m_k)
    for (int i = lane; i < NBANK * DD * DD; i += 32) {
        int b = i / (DD * DD);
        ((float*)g_Sb[b][k])[i - b * DD * DD] = 0.f;
    }
    for (int i = lane; i < NBANK * DD; i += 32) g_sumxb[i >> 5][k][i & 31] = 0.f;
    if (lane < NBANK) g_nkb[lane][k] = 0.f;

    // Cholesky (lower), lane = row
    for (int j = 0; j < DD; j++) {
        float ljj = sqrtf(A[j][j]);
        __syncwarp();
        if (lane == j) A[j][j] = ljj;
        else if (lane > j) A[lane][j] = A[lane][j] / ljj;
        __syncwarp();
        if (lane > j) {
            float lij = A[lane][j];
            for (int c2 = j + 1; c2 <= lane; c2++) A[lane][c2] -= lij * A[c2][j];
        }
        __syncwarp();
    }

    float logdet = 0.f;
    for (int j = 0; j < DD; j++) logdet += logf(A[j][j]);

    // P = L^{-T} L^{-1}; lane computes column `lane`
    float y[DD];
#pragma unroll
    for (int r = 0; r < DD; r++) y[r] = (r == lane) ? 1.f : 0.f;
#pragma unroll
    for (int j = 0; j < DD; j++) {
        y[j] = y[j] / A[j][j];
#pragma unroll
        for (int i2 = j + 1; i2 < DD; i2++) y[i2] -= A[i2][j] * y[j];
    }
#pragma unroll
    for (int j = DD - 1; j >= 0; j--) {
        y[j] = y[j] / A[j][j];
#pragma unroll
        for (int i2 = 0; i2 < j; i2++) y[i2] -= A[j][i2] * y[j];
    }
    __syncwarp();
#pragma unroll
    for (int r = 0; r < DD; r++) A[r][lane] = y[r];   // A := P
    __syncwarp();

    // b = P * mu
    float b = 0.f;
    for (int j = 0; j < DD; j++) b += A[lane][j] * g_means[k][j];
    bsh[lane] = b;
    float cv = b * g_means[k][lane];
    for (int o = 16; o; o >>= 1) cv += __shfl_xor_sync(0xffffffff, cv, o);
    if (lane == 0)
        csh = logf(g_w[k]) - logdet - 0.5f * cv - 0.5f * (float)DD * LOG2PIF;
    __syncwarp();

    // pack coefs (augmented x, x[32]=1): terms (i,j) 0<=i<=j<=32, consecutive-j pairs
    for (int q = lane; q < NQ; q += 32) {
        int i = 0, qq = q;
        while (true) {
            int np = (34 - i) >> 1;
            if (qq < np) break;
            qq -= np; i++;
        }
        int j = i + 2 * qq;
        float c0, c1;
        {
            int jj = j;
            if (i == 32) c0 = csh;
            else if (jj == 32) c0 = bsh[i];
            else c0 = (i == jj ? -0.5f : -1.0f) * A[i][jj];
        }
        if (j + 1 <= 32) {
            int jj = j + 1;
            if (jj == 32) c1 = bsh[i];
            else c1 = (i == jj ? -0.5f : -1.0f) * A[i][jj];
        } else c1 = 0.f;
        g_cf2[q * 32 + k * 2] = c0;
        g_cf2[q * 32 + k * 2 + 1] = c1;
    }
}

// ---------------- E kernel: 2 samples/thread, f32x2, 255-reg budget ----------------
__global__ void __launch_bounds__(256, 1) e_k(const float* __restrict__ X,
                                              float* __restrict__ out,
                                              int N, int mode) {
    __shared__ __align__(16) float cf[NQ * 32];
    for (int i = threadIdx.x; i < NQ * 8; i += 256)
        ((float4*)cf)[i] = ((const float4*)g_cf2)[i];
    __syncthreads();

    int n0 = (blockIdx.x * 256 + threadIdx.x) * 2;
    int n1 = n0 + 1;
    bool vA = n0 < N, vB = n1 < N;
    if (!vA) return;

    float xa[34], xb[34];
    {
        const float4* xp = (const float4*)(X + (size_t)n0 * DD);
#pragma unroll
        for (int j4 = 0; j4 < 8; j4++) {
            float4 v = xp[j4];
            xa[j4 * 4 + 0] = v.x; xa[j4 * 4 + 1] = v.y;
            xa[j4 * 4 + 2] = v.z; xa[j4 * 4 + 3] = v.w;
        }
        const float4* xq = (const float4*)(X + (size_t)(vB ? n1 : n0) * DD);
#pragma unroll
        for (int j4 = 0; j4 < 8; j4++) {
            float4 v = xq[j4];
            xb[j4 * 4 + 0] = v.x; xb[j4 * 4 + 1] = v.y;
            xb[j4 * 4 + 2] = v.z; xb[j4 * 4 + 3] = v.w;
        }
    }
    xa[32] = 1.f; xa[33] = 0.f;
    xb[32] = 1.f; xb[33] = 0.f;

    ull lpa[KC], lpb[KC];
#pragma unroll
    for (int k = 0; k < KC; k++) { lpa[k] = 0ull; lpb[k] = 0ull; }

    int q = 0;
#pragma unroll
    for (int i = 0; i < 33; i++) {
        ull xia = pk(xa[i], xa[i]);
        ull xib = pk(xb[i], xb[i]);
#pragma unroll
        for (int j = i; j < 33; j += 2) {
            ull xxa = mul2(xia, pk(xa[j], xa[j + 1]));
            ull xxb = mul2(xib, pk(xb[j], xb[j + 1]));
            const float* cq = cf + q * 32;
#pragma unroll
            for (int kb = 0; kb < 8; kb++) {
                ulonglong2 cc = *(const ulonglong2*)(cq + kb * 4);
                ffma2(lpa[kb * 2 + 0], cc.x, xxa);
                ffma2(lpa[kb * 2 + 1], cc.y, xxa);
                ffma2(lpb[kb * 2 + 0], cc.x, xxb);
                ffma2(lpb[kb * 2 + 1], cc.y, xxb);
            }
            q++;
        }
    }

    // epilogue (both samples)
    float la[KC], lb[KC];
#pragma unroll
    for (int k = 0; k < KC; k++) {
        float2 fa = upk(lpa[k]); la[k] = fa.x + fa.y;
        float2 fb = upk(lpb[k]); lb[k] = fb.x + fb.y;
    }
    float ma = la[0], mb = lb[0];
#pragma unroll
    for (int k = 1; k < KC; k++) { ma = fmaxf(ma, la[k]); mb = fmaxf(mb, lb[k]); }
    float sa = 0.f, sb = 0.f;
#pragma unroll
    for (int k = 0; k < KC; k++) {
        la[k] = __expf(la[k] - ma); sa += la[k];
        lb[k] = __expf(lb[k] - mb); sb += lb[k];
    }

    if (mode == 1) {
        out[n0] = ma + __logf(sa);
        if (vB) out[n1] = mb + __logf(sb);
    } else {
        float ia = 1.f / sa, ib = 1.f / sb;
        float4* rp = (float4*)(g_resp + (size_t)n0 * KC);
#pragma unroll
        for (int k4 = 0; k4 < 4; k4++)
            rp[k4] = make_float4(la[k4 * 4 + 0] * ia, la[k4 * 4 + 1] * ia,
                                 la[k4 * 4 + 2] * ia, la[k4 * 4 + 3] * ia);
        if (vB) {
            float4* rq = (float4*)(g_resp + (size_t)n1 * KC);
#pragma unroll
            for (int k4 = 0; k4 < 4; k4++)
                rq[k4] = make_float4(lb[k4 * 4 + 0] * ib, lb[k4 * 4 + 1] * ib,
                                     lb[k4 * 4 + 2] * ib, lb[k4 * 4 + 3] * ib);
        }
    }
}

// ---------------- M kernel: 512 threads, thread = (k, one row), high occupancy ----------------
__global__ void __launch_bounds__(512) m_k(const float* __restrict__ X,
                                           int N, int ntiles) {
    __shared__ __align__(16) float x2[TM * 36];
    __shared__ float rs[TM * 17];
    int tid = threadIdx.x;
    int k = tid & 15;
    int i = tid >> 4;          // 0..31

    ull acc[16];
#pragma unroll
    for (int m = 0; m < 16; m++) acc[m] = 0ull;
    float aX = 0.f, aN = 0.f;

    for (int tile = blockIdx.x; tile < ntiles; tile += gridDim.x) {
        int base = tile * TM;
        int cnt = N - base; if (cnt > TM) cnt = TM;
        __syncthreads();
        for (int e = tid; e < TM * DD; e += 512) {
            int s = e >> 5, d = e & 31;
            x2[s * 36 + d] = (s < cnt) ? X[(size_t)(base + s) * DD + d] : 0.f;
        }
        for (int e = tid; e < TM * KC; e += 512) {
            int s = e >> 4, kk = e & 15;
            rs[s * 17 + kk] = (s < cnt) ? g_resp[(size_t)(base + s) * KC + kk] : 0.f;
        }
        __syncthreads();

#pragma unroll 2
        for (int t = 0; t < TM; t++) {
            float r = rs[t * 17 + k];
            float xi = x2[t * 36 + i];
            float u = r * xi;
            aX += u;
            if (i == 0) aN += r;
            ull u2 = pk(u, u);
            const ulonglong2* xv = (const ulonglong2*)&x2[t * 36];
#pragma unroll
            for (int j2 = 0; j2 < 8; j2++) {
                ulonglong2 v = xv[j2];
                ffma2(acc[j2 * 2 + 0], u2, v.x);
                ffma2(acc[j2 * 2 + 1], u2, v.y);
            }
        }
    }

    int bank = blockIdx.x & (NBANK - 1);
#pragma unroll
    for (int m = 0; m < 16; m++) {
        float2 a = upk(acc[m]);
        atomicAdd(&g_Sb[bank][k][i][2 * m + 0], a.x);
        atomicAdd(&g_Sb[bank][k][i][2 * m + 1], a.y);
    }
    atomicAdd(&g_sumxb[bank][k][i], aX);
    if (i == 0) atomicAdd(&g_nkb[bank][k], aN);
}

// ---------------- host launcher ----------------
extern "C" void kernel_launch(void* const* d_in, const int* in_sizes, int n_in,
                              void* d_out, int out_size) {
    const float* X = (const float*)d_in[0];
    const float* w = (const float*)d_in[1];
    const float* m = (const float*)d_in[2];
    const float* c = (const float*)d_in[3];
    float* out = (float*)d_out;

    int N = in_sizes[0] / DD;
    int ntiles = (N + TM - 1) / TM;
    int egrid = (N + 511) / 512;
    int mgrid = 296;
    if (mgrid > ntiles) mgrid = ntiles;

    init_k<<<34, 512>>>(w, m, c);
    for (int it = 0; it < 5; it++) {       // n_iter = 5 (fixed problem instance)
        prep_k<<<KC, 32>>>(N, it == 0 ? 1 : 0);
        e_k<<<egrid, 256>>>(X, nullptr, N, 0);
        m_k<<<mgrid, 512>>>(X, N, ntiles);
    }
    prep_k<<<KC, 32>>>(N, 0);
    e_k<<<egrid, 256>>>(X, out, N, 1);
}